// round 16
// baseline (speedup 1.0000x reference)
#include <cuda_runtime.h>

// ConvolutionalCapsule EM-routing, fully fused, one CTA (256 thr) per position.
// R12 architecture (votes only in registers, reduce-scatter M-step) +
//  1) E-step expanded quadratic (2 FMA/elem), constants (iv,B) streamed from
//     SMEM in k-groups with j-inner loop interchange -> only ~13 extra live
//     regs (R15's A[16]/Bv[16] arrays caused 255-reg spill).
//  2) lstd = 0.5*log(max(var,1e-18)) — no sqrt.

#define BATCH   8
#define HW      14
#define OHW     12
#define NPOS    (BATCH * OHW * OHW)   // 1152
#define NI      144
#define RSTR    144                   // floats per o in rr'
#define CAP_EPS 1e-9f

// SMEM layout (floats)
#define OFF_RP   2880                 // pose: 144*20
#define OFF_Z    (OFF_RP + 16*RSTR)   // +2304
#define OFF_A    (OFF_Z + NI*17)      // +2448
#define OFF_MIV  (OFF_A + NI)         // +144   (miv: 256 float2 = 512 floats)
#define SMEM_FLOATS (OFF_MIV + 512)   // 8288
#define SMEM_BYTES  (SMEM_FLOATS * 4) // 33152 B

// 16-lane reduce-scatter over lane bits 0..3: lane c ends with sum_lanes T[c].
#define SCATTER16(T) {                                                     \
    _Pragma("unroll")                                                      \
    for (int m_ = 8; m_ >= 1; m_ >>= 1) {                                  \
        const bool hi_ = (c & m_) != 0;                                    \
        _Pragma("unroll")                                                  \
        for (int k_ = 0; k_ < m_; k_++) {                                  \
            float send_ = hi_ ? T[k_] : T[k_ + m_];                        \
            float recv_ = __shfl_xor_sync(0xffffffffu, send_, m_);         \
            T[k_] = (hi_ ? T[k_ + m_] : T[k_]) + recv_;                    \
        }                                                                  \
    } }

__global__ __launch_bounds__(256, 1)
void capsule_em_kernel(const float* __restrict__ g_pose,
                       const float* __restrict__ g_act,
                       const float* __restrict__ g_w,
                       const float* __restrict__ g_bv,
                       const float* __restrict__ g_ba,
                       float* __restrict__ out)
{
    extern __shared__ float sm[];
    float* pose_sh = sm;              // [i*20 + 4*x + y]
    float* rp_sm   = sm + OFF_RP;     // rr' = rr * a, [o*144 + i]
    float* z_sm    = sm + OFF_Z;      // [i*17 + o]
    float* a_sh    = sm + OFF_A;      // [i]
    float2* miv_sm = (float2*)(sm + OFF_MIV);   // [o*16 + e] = (iv, -2*m*iv)

    const int tid  = threadIdx.x;
    const int o    = tid >> 4;        // output capsule
    const int c    = tid & 15;        // i_lo; owns pose elem e=c after scatter

    const int n   = blockIdx.x;
    const int b   = n / (OHW * OHW);
    const int rem = n - b * (OHW * OHW);
    const int h0  = rem / OHW;
    const int w0  = rem - h0 * OHW;

    // ---- Stage pose tile + activations ----
    {
        const float4* gp4 = (const float4*)g_pose;
        float4* ps4 = (float4*)pose_sh;
        #pragma unroll
        for (int idx = tid; idx < 576; idx += 256) {
            int kk = idx >> 6;            // patch 0..8
            int c4 = idx & 63;            // cap*4 + x
            int di = kk / 3, dj = kk - di * 3;
            int pix = (b * HW + h0 + di) * HW + (w0 + dj);
            int cap = c4 >> 2, x = c4 & 3;
            ps4[(kk * 16 + cap) * 5 + x] = gp4[pix * 64 + c4];
        }
        if (tid < NI) {
            int kk = tid >> 4;
            int cap = tid & 15;
            int di = kk / 3, dj = kk - di * 3;
            int pix = (b * HW + h0 + di) * HW + (w0 + dj);
            a_sh[tid] = g_act[pix * 16 + cap];
        }
    }
    __syncthreads();

    // ---- Votes into registers + t=0 moments in-flight ----
    // v[j*16 + 4x + z] = sum_y pose[i][x][y] * w[i][o][y][z], i = c + 16j.
    float v[144];
    float T0 = 0.0f, T1[16], T2[16];
    #pragma unroll
    for (int e = 0; e < 16; e++) { T1[e] = 0.0f; T2[e] = 0.0f; }
    {
        const float4* w4 = (const float4*)g_w;       // [i*64 + o*4 + y]
        const float4* p4 = (const float4*)pose_sh;   // [i*5 + x]
        #pragma unroll
        for (int j = 0; j < 9; j++) {
            int i = c + 16 * j;
            float ai = a_sh[i] * 0.0625f;            // rr(1/16) * a
            float4 pr0 = p4[i * 5 + 0];
            float4 pr1 = p4[i * 5 + 1];
            float4 pr2 = p4[i * 5 + 2];
            float4 pr3 = p4[i * 5 + 3];
            float4 wr0 = w4[i * 64 + o * 4 + 0];
            float4 wr1 = w4[i * 64 + o * 4 + 1];
            float4 wr2 = w4[i * 64 + o * 4 + 2];
            float4 wr3 = w4[i * 64 + o * 4 + 3];
            T0 += ai;
            #define VROW(PR, X) {                                           \
                float e0 = PR.x*wr0.x + PR.y*wr1.x + PR.z*wr2.x + PR.w*wr3.x; \
                float e1 = PR.x*wr0.y + PR.y*wr1.y + PR.z*wr2.y + PR.w*wr3.y; \
                float e2 = PR.x*wr0.z + PR.y*wr1.z + PR.z*wr2.z + PR.w*wr3.z; \
                float e3 = PR.x*wr0.w + PR.y*wr1.w + PR.z*wr2.w + PR.w*wr3.w; \
                v[j*16 + 4*(X) + 0] = e0;  v[j*16 + 4*(X) + 1] = e1;          \
                v[j*16 + 4*(X) + 2] = e2;  v[j*16 + 4*(X) + 3] = e3;          \
                T1[4*(X)+0] = fmaf(ai, e0, T1[4*(X)+0]);                      \
                T2[4*(X)+0] = fmaf(ai * e0, e0, T2[4*(X)+0]);                 \
                T1[4*(X)+1] = fmaf(ai, e1, T1[4*(X)+1]);                      \
                T2[4*(X)+1] = fmaf(ai * e1, e1, T2[4*(X)+1]);                 \
                T1[4*(X)+2] = fmaf(ai, e2, T1[4*(X)+2]);                      \
                T2[4*(X)+2] = fmaf(ai * e2, e2, T2[4*(X)+2]);                 \
                T1[4*(X)+3] = fmaf(ai, e3, T1[4*(X)+3]);                      \
                T2[4*(X)+3] = fmaf(ai * e3, e3, T2[4*(X)+3]); }
            VROW(pr0, 0)
            VROW(pr1, 1)
            VROW(pr2, 2)
            VROW(pr3, 3)
            #undef VROW
        }
    }

    // ---- EM routing ----
    const float bvo = g_bv[o];
    const float bao = g_ba[o];
    float mean = 0.0f, act = 0.0f;

    #pragma unroll 1
    for (int t = 0; t < 3; t++) {
        const float inv_temp = 1.0f + (float)t;

        if (t > 0) {
            // M-step t=1,2: accumulate moments from register votes
            T0 = 0.0f;
            #pragma unroll
            for (int e = 0; e < 16; e++) { T1[e] = 0.0f; T2[e] = 0.0f; }
            #pragma unroll
            for (int j = 0; j < 9; j++) {
                float q = rp_sm[o * RSTR + c + 16 * j];
                T0 += q;
                #pragma unroll
                for (int e = 0; e < 16; e++) {
                    float vv = v[j*16 + e];
                    T1[e] = fmaf(q, vv, T1[e]);
                    T2[e] = fmaf(q * vv, vv, T2[e]);
                }
            }
        }

        // S0: allreduce over the 16 i_lo lanes
        float S0 = T0;
        #pragma unroll
        for (int m = 8; m >= 1; m >>= 1)
            S0 += __shfl_xor_sync(0xffffffffu, S0, m);
        // S1/S2: reduce-scatter -> lane c owns pose element e = c
        SCATTER16(T1)
        SCATTER16(T2)
        float S1 = T1[0];
        float S2 = T2[0];

        float invS0 = __fdividef(1.0f, S0);
        mean = S1 * invS0;
        float var  = fmaxf(S2 * invS0 - mean * mean, 1e-18f);
        float lstd = 0.5f * __logf(var);   // == log(sqrt(var)+1e-9) to ~1e-9

        // L = sum over the 16 pose elems (held one-per-lane)
        float L = lstd;
        #pragma unroll
        for (int m = 8; m >= 1; m >>= 1)
            L += __shfl_xor_sync(0xffffffffu, L, m);

        float cost = S0 * (16.0f * bvo + L);
        act = 1.0f / (1.0f + __expf(-inv_temp * (bao - cost)));

        if (t < 2) {
            // E-step: expanded quadratic, constants streamed, j-inner.
            // (v-m)^2*iv = (iv*v + B)*v + m^2*iv,  B = -2*m*iv.
            float iv   = __fdividef(1.0f, 2.0f * var + CAP_EPS);
            float Bc   = -2.0f * mean * iv;
            float cown = -0.5f * mean * Bc;        // m^2 * iv
            float C = cown;
            #pragma unroll
            for (int m = 8; m >= 1; m >>= 1)
                C += __shfl_xor_sync(0xffffffffu, C, m);
            float zc = __logf(act + CAP_EPS) - L - C;

            // publish (iv, B) for my elem; consumers are in this warp
            miv_sm[o * 16 + c] = make_float2(iv, Bc);
            __syncwarp();

            float s[9];
            #pragma unroll
            for (int j = 0; j < 9; j++) s[j] = 0.0f;
            {
                const float4* q4 = (const float4*)(miv_sm + o * 16);
                #pragma unroll
                for (int k = 0; k < 8; k++) {       // elem pair (2k, 2k+1)
                    float4 q = q4[k];               // (iv0,B0,iv1,B1) broadcast
                    #pragma unroll
                    for (int j = 0; j < 9; j++) {
                        float v0 = v[j*16 + 2*k];
                        float v1 = v[j*16 + 2*k + 1];
                        s[j] = fmaf(fmaf(q.x, v0, q.y), v0, s[j]);
                        s[j] = fmaf(fmaf(q.z, v1, q.w), v1, s[j]);
                    }
                }
            }
            #pragma unroll
            for (int j = 0; j < 9; j++)
                z_sm[(c + 16 * j) * 17 + o] = zc - s[j];
            __syncthreads();

            // softmax over o per input capsule i (144 threads, 16 o's each)
            if (tid < NI) {
                float zr[16];
                float zmax = -1e30f;
                #pragma unroll
                for (int oo = 0; oo < 16; oo++) {
                    zr[oo] = z_sm[tid * 17 + oo];
                    zmax = fmaxf(zmax, zr[oo]);
                }
                float se = 0.0f;
                #pragma unroll
                for (int oo = 0; oo < 16; oo++) {
                    zr[oo] = __expf(zr[oo] - zmax);
                    se += zr[oo];
                }
                float scale = __fdividef(a_sh[tid], se);
                #pragma unroll
                for (int oo = 0; oo < 16; oo++)
                    rp_sm[oo * RSTR + tid] = zr[oo] * scale;
            }
            __syncthreads();
        }
    }

    // ---- Outputs: pose [N,16,4,4] then activation [N,16] ----
    out[n * 256 + o * 16 + c] = mean;    // lane c owns pose element e=c
    if (c == 0) out[NPOS * 256 + n * 16 + o] = act;
}

extern "C" void kernel_launch(void* const* d_in, const int* in_sizes, int n_in,
                              void* d_out, int out_size)
{
    const float* g_pose = (const float*)d_in[0];
    const float* g_act  = (const float*)d_in[1];
    const float* g_w    = (const float*)d_in[2];
    const float* g_bv   = (const float*)d_in[3];
    const float* g_ba   = (const float*)d_in[4];
    float* out = (float*)d_out;

    cudaFuncSetAttribute(capsule_em_kernel,
                         cudaFuncAttributeMaxDynamicSharedMemorySize, SMEM_BYTES);
    capsule_em_kernel<<<NPOS, 256, SMEM_BYTES>>>(g_pose, g_act, g_w, g_bv, g_ba, out);
}